// round 1
// baseline (speedup 1.0000x reference)
#include <cuda_runtime.h>
#include <cuda_bf16.h>
#include <math.h>

// ---------------- problem constants ----------------
#define NB    16
#define PP    1024
#define NP    (NB*PP)          // 16384
#define KNN   16
#define DIMS  3
#define C_IN  128
#define C_MID 64
#define C_CAT 192              // C_MID + C_IN
#define C_OUT 256
#define DM    2
#define CD    384              // C_CAT*DM
#define KK    256              // KNN*KNN
#define EPSBN 1e-5f

// ---------------- scratch (device globals; no allocs allowed) ----------------
__device__ float g_pl   [NP*KNN*DIMS];      // pts_local, viewed [NP*16,3] or [NP,48]
__device__ float g_lift [NP*KNN*C_MID];     // fts_lifted [NP,16,64]
__device__ float g_Xa   [NP*KK];            // X ping
__device__ float g_Xb   [NP*KK];            // X pong
__device__ float g_dw   [NP*CD];            // depthwise output [NP,384]
__device__ float g_wc   [48*KK];            // cv_w transposed  [j=k*3+d][o]
__device__ float g_pwT  [CD*C_OUT];         // pw_w transposed  [j][o]
__device__ float g_psum [C_OUT*128];        // per-(channel, mtile) partial sums
__device__ float g_psq  [C_OUT*128];
__device__ float g_scale[C_OUT];
__device__ float g_shift[C_OUT];

// ---------------- prep: pts_local + weight transposes ----------------
__global__ void prep_kernel(const float* __restrict__ rep, const float* __restrict__ pts,
                            const float* __restrict__ cvw, const float* __restrict__ pww) {
    int idx = blockIdx.x * blockDim.x + threadIdx.x;
    if (idx < NP*KNN*DIMS) {
        int d  = idx % DIMS;
        int pk = idx / DIMS;
        int p  = pk / KNN;
        g_pl[idx] = pts[idx] - rep[p*DIMS + d];
    }
    if (idx < 48*KK) {
        int o = idx % KK, j = idx / KK;
        int k = j / 3, d = j % 3;
        g_wc[idx] = cvw[o*48 + d*KNN + k];   // cv_w[o][d][k]
    }
    if (idx < CD*C_OUT) {
        int o = idx % C_OUT, j = idx / C_OUT;
        g_pwT[idx] = pww[o*CD + j];          // pw_w[o][j]
    }
}

// ---------------- generic tiled SGEMM: C = act(A[MxK] @ B[KxN] + bias) ----------------
template<int BM,int BN,int BK,int TM,int TN,bool RELU,bool BIAS>
__global__ void sgemm_kernel(const float* __restrict__ A, const float* __restrict__ B,
                             const float* __restrict__ bias, float* __restrict__ C,
                             int M, int N, int K) {
    constexpr int THREADS = (BM/TM)*(BN/TN);
    __shared__ float As[BK][BM];
    __shared__ float Bs[BK][BN];
    const int tid = threadIdx.x;
    const int tx  = tid % (BN/TN);
    const int ty  = tid / (BN/TN);
    const int rowBase = blockIdx.y * BM;
    const int colBase = blockIdx.x * BN;
    float acc[TM][TN];
    #pragma unroll
    for (int i = 0; i < TM; i++)
        #pragma unroll
        for (int j = 0; j < TN; j++) acc[i][j] = 0.f;

    for (int k0 = 0; k0 < K; k0 += BK) {
        #pragma unroll
        for (int e = tid; e < BM*BK; e += THREADS) {
            int r = e / BK, c = e % BK;
            As[c][r] = (k0 + c < K) ? A[(size_t)(rowBase + r)*K + k0 + c] : 0.f;
        }
        #pragma unroll
        for (int e = tid; e < BK*BN; e += THREADS) {
            int r = e / BN, c = e % BN;
            Bs[r][c] = (k0 + r < K) ? B[(size_t)(k0 + r)*N + colBase + c] : 0.f;
        }
        __syncthreads();
        #pragma unroll
        for (int kk = 0; kk < BK; kk++) {
            float ra[TM], rb[TN];
            #pragma unroll
            for (int i = 0; i < TM; i++) ra[i] = As[kk][ty*TM + i];
            #pragma unroll
            for (int j = 0; j < TN; j++) rb[j] = Bs[kk][tx*TN + j];
            #pragma unroll
            for (int i = 0; i < TM; i++)
                #pragma unroll
                for (int j = 0; j < TN; j++) acc[i][j] += ra[i]*rb[j];
        }
        __syncthreads();
    }
    #pragma unroll
    for (int j = 0; j < TN; j++) {
        int c = colBase + tx*TN + j;
        float bv = BIAS ? bias[c] : 0.f;
        #pragma unroll
        for (int i = 0; i < TM; i++) {
            float v = acc[i][j] + bv;
            if (RELU) v = fmaxf(v, 0.f);
            C[(size_t)(rowBase + ty*TM + i)*N + c] = v;
        }
    }
}

// ---------------- fused lift MLP: lift = relu(relu(pl@d1+b1)@d2+b2) ----------------
// M = NP*16 rows, N = 64, K = 64. d1 stage (K=3) is computed inline in the A loader.
__global__ void lift_fused_kernel(const float* __restrict__ pl,
                                  const float* __restrict__ d1w, const float* __restrict__ d1b,
                                  const float* __restrict__ d2w, const float* __restrict__ d2b,
                                  float* __restrict__ out) {
    constexpr int BM=128, BN=64, BK=16, TM=8, TN=4, THREADS=256;
    __shared__ float As[BK][BM];
    __shared__ float Bs[BK][BN];
    const int tid = threadIdx.x;
    const int tx  = tid % (BN/TN);
    const int ty  = tid / (BN/TN);
    const int rowBase = blockIdx.x * BM;
    float acc[TM][TN];
    #pragma unroll
    for (int i = 0; i < TM; i++)
        #pragma unroll
        for (int j = 0; j < TN; j++) acc[i][j] = 0.f;

    for (int k0 = 0; k0 < C_MID; k0 += BK) {
        #pragma unroll
        for (int e = tid; e < BM*BK; e += THREADS) {
            int r = e / BK, c = e % BK;
            int row  = rowBase + r;
            int kcol = k0 + c;
            float p0 = pl[row*3+0], p1 = pl[row*3+1], p2 = pl[row*3+2];
            float h = p0*d1w[kcol] + p1*d1w[64+kcol] + p2*d1w[128+kcol] + d1b[kcol];
            As[c][r] = fmaxf(h, 0.f);
        }
        #pragma unroll
        for (int e = tid; e < BK*BN; e += THREADS) {
            int r = e / BN, c = e % BN;
            Bs[r][c] = d2w[(k0 + r)*C_MID + c];
        }
        __syncthreads();
        #pragma unroll
        for (int kk = 0; kk < BK; kk++) {
            float ra[TM], rb[TN];
            #pragma unroll
            for (int i = 0; i < TM; i++) ra[i] = As[kk][ty*TM + i];
            #pragma unroll
            for (int j = 0; j < TN; j++) rb[j] = Bs[kk][tx*TN + j];
            #pragma unroll
            for (int i = 0; i < TM; i++)
                #pragma unroll
                for (int j = 0; j < TN; j++) acc[i][j] += ra[i]*rb[j];
        }
        __syncthreads();
    }
    #pragma unroll
    for (int j = 0; j < TN; j++) {
        int c = tx*TN + j;
        float bv = d2b[c];
        #pragma unroll
        for (int i = 0; i < TM; i++) {
            float v = fmaxf(acc[i][j] + bv, 0.f);
            out[(size_t)(rowBase + ty*TM + i)*C_MID + c] = v;
        }
    }
}

// ---------------- per-point: fts_X = X @ fts_cat ; depthwise -> dw ----------------
#define DPTS 8
__global__ void xform_dw_kernel(const float* __restrict__ X2,
                                const float* __restrict__ lift,
                                const float* __restrict__ fts,
                                const float* __restrict__ dww,
                                const float* __restrict__ dwb,
                                float* __restrict__ dwout) {
    __shared__ float s_dwt[32*C_CAT];     // transposed dw_w: [(m*16+i)][c]
    __shared__ float s_fc[KNN][C_CAT];    // fts_cat for one point
    __shared__ float s_X[KK];             // X matrix (row-major 16x16)
    const int tid = threadIdx.x;          // 128 threads

    for (int e = tid; e < 32*C_CAT; e += 128) {
        int mi = e / C_CAT, c = e % C_CAT;
        s_dwt[mi*C_CAT + c] = dww[c*32 + mi];     // dw_w[c][m][i], mi = m*16+i
    }
    __syncthreads();

    for (int pp = 0; pp < DPTS; pp++) {
        int p = blockIdx.x * DPTS + pp;
        for (int e = tid; e < KK; e += 128) s_X[e] = X2[(size_t)p*KK + e];
        for (int e = tid; e < KNN*C_CAT; e += 128) {
            int j = e / C_CAT, c = e % C_CAT;
            s_fc[j][c] = (c < C_MID) ? lift[(size_t)p*(KNN*C_MID) + j*C_MID + c]
                                     : fts [(size_t)p*(KNN*C_IN) + j*C_IN + (c - C_MID)];
        }
        __syncthreads();
        for (int c = tid; c < C_CAT; c += 128) {
            float v[KNN];
            #pragma unroll
            for (int i = 0; i < KNN; i++) v[i] = 0.f;
            #pragma unroll
            for (int j = 0; j < KNN; j++) {
                float f = s_fc[j][c];
                #pragma unroll
                for (int i = 0; i < KNN; i++) v[i] += s_X[i*KNN + j] * f;
            }
            #pragma unroll
            for (int m = 0; m < DM; m++) {
                float s = 0.f;
                #pragma unroll
                for (int i = 0; i < KNN; i++) s += v[i] * s_dwt[(m*16 + i)*C_CAT + c];
                dwout[(size_t)p*CD + c*DM + m] = s + dwb[c*DM + m];
            }
        }
        __syncthreads();
    }
}

// ---------------- pointwise GEMM + ReLU + deterministic BN partials ----------------
// M=16384, N=256, K=384 ; BM=BN=128, BK=16, TM=TN=8 ; grid (2, 128)
__global__ void sgemm_pw_stats(const float* __restrict__ A, const float* __restrict__ B,
                               float* __restrict__ C,
                               float* __restrict__ psum, float* __restrict__ psq) {
    __shared__ float As[16][128];
    __shared__ float Bs[16][128];
    const int tid = threadIdx.x;
    const int tx = tid % 16, ty = tid / 16;
    const int rowBase = blockIdx.y * 128;
    const int colBase = blockIdx.x * 128;
    float acc[8][8];
    #pragma unroll
    for (int i = 0; i < 8; i++)
        #pragma unroll
        for (int j = 0; j < 8; j++) acc[i][j] = 0.f;

    for (int k0 = 0; k0 < CD; k0 += 16) {
        #pragma unroll
        for (int e = tid; e < 128*16; e += 256) {
            int r = e / 16, c = e % 16;
            As[c][r] = A[(size_t)(rowBase + r)*CD + k0 + c];
        }
        #pragma unroll
        for (int e = tid; e < 16*128; e += 256) {
            int r = e / 128, c = e % 128;
            Bs[r][c] = B[(size_t)(k0 + r)*C_OUT + colBase + c];
        }
        __syncthreads();
        #pragma unroll
        for (int kk = 0; kk < 16; kk++) {
            float ra[8], rb[8];
            #pragma unroll
            for (int i = 0; i < 8; i++) ra[i] = As[kk][ty*8 + i];
            #pragma unroll
            for (int j = 0; j < 8; j++) rb[j] = Bs[kk][tx*8 + j];
            #pragma unroll
            for (int i = 0; i < 8; i++)
                #pragma unroll
                for (int j = 0; j < 8; j++) acc[i][j] += ra[i]*rb[j];
        }
        __syncthreads();
    }
    float cs[8], cq[8];
    #pragma unroll
    for (int j = 0; j < 8; j++) { cs[j] = 0.f; cq[j] = 0.f; }
    #pragma unroll
    for (int j = 0; j < 8; j++) {
        int c = colBase + tx*8 + j;
        #pragma unroll
        for (int i = 0; i < 8; i++) {
            float v = fmaxf(acc[i][j], 0.f);
            C[(size_t)(rowBase + ty*8 + i)*C_OUT + c] = v;
            cs[j] += v;
            cq[j] += v*v;
        }
    }
    __syncthreads();
    float* sb = &As[0][0];   // reuse smem: [16][128]
    float* qb = &Bs[0][0];
    #pragma unroll
    for (int j = 0; j < 8; j++) {
        sb[ty*128 + tx*8 + j] = cs[j];
        qb[ty*128 + tx*8 + j] = cq[j];
    }
    __syncthreads();
    if (tid < 128) {
        float s = 0.f, q = 0.f;
        #pragma unroll
        for (int t = 0; t < 16; t++) { s += sb[t*128 + tid]; q += qb[t*128 + tid]; }
        psum[(colBase + tid)*128 + blockIdx.y] = s;
        psq [(colBase + tid)*128 + blockIdx.y] = q;
    }
}

// ---------------- BN stats -> scale/shift ----------------
__global__ void stats_kernel(const float* __restrict__ psum, const float* __restrict__ psq,
                             const float* __restrict__ bng, const float* __restrict__ bnb) {
    int o = threadIdx.x;   // 256 threads
    float s = 0.f, q = 0.f;
    for (int t = 0; t < 128; t++) { s += psum[o*128 + t]; q += psq[o*128 + t]; }
    float mean = s * (1.f / (float)NP);
    float var  = q * (1.f / (float)NP) - mean*mean;
    float sc   = bng[o] * rsqrtf(var + EPSBN);
    g_scale[o] = sc;
    g_shift[o] = bnb[o] - mean*sc;
}

// ---------------- BN apply (in place, float4) ----------------
__global__ void bn_apply_kernel(float* __restrict__ out) {
    int idx = blockIdx.x * blockDim.x + threadIdx.x;   // NP*64 float4 groups
    if (idx >= NP*(C_OUT/4)) return;
    int c4 = (idx & 63) * 4;
    float4 v = reinterpret_cast<float4*>(out)[idx];
    v.x = v.x * g_scale[c4+0] + g_shift[c4+0];
    v.y = v.y * g_scale[c4+1] + g_shift[c4+1];
    v.z = v.z * g_scale[c4+2] + g_shift[c4+2];
    v.w = v.w * g_scale[c4+3] + g_shift[c4+3];
    reinterpret_cast<float4*>(out)[idx] = v;
}

// ---------------- launch ----------------
extern "C" void kernel_launch(void* const* d_in, const int* in_sizes, int n_in,
                              void* d_out, int out_size) {
    const float* rep  = (const float*)d_in[0];
    const float* pts  = (const float*)d_in[1];
    const float* fts  = (const float*)d_in[2];
    const float* d1w  = (const float*)d_in[3];
    const float* d1b  = (const float*)d_in[4];
    const float* d2w  = (const float*)d_in[5];
    const float* d2b  = (const float*)d_in[6];
    const float* cvw  = (const float*)d_in[7];
    const float* cvb  = (const float*)d_in[8];
    const float* x1w  = (const float*)d_in[9];
    const float* x1b  = (const float*)d_in[10];
    const float* x2w  = (const float*)d_in[11];
    const float* x2b  = (const float*)d_in[12];
    const float* dww  = (const float*)d_in[13];
    const float* dwb  = (const float*)d_in[14];
    const float* bng  = (const float*)d_in[16];
    const float* bnb  = (const float*)d_in[17];
    float* out = (float*)d_out;

    float *pl, *lift, *Xa, *Xb, *dw, *wc, *pwT, *psum, *psq;
    cudaGetSymbolAddress((void**)&pl,   g_pl);
    cudaGetSymbolAddress((void**)&lift, g_lift);
    cudaGetSymbolAddress((void**)&Xa,   g_Xa);
    cudaGetSymbolAddress((void**)&Xb,   g_Xb);
    cudaGetSymbolAddress((void**)&dw,   g_dw);
    cudaGetSymbolAddress((void**)&wc,   g_wc);
    cudaGetSymbolAddress((void**)&pwT,  g_pwT);
    cudaGetSymbolAddress((void**)&psum, g_psum);
    cudaGetSymbolAddress((void**)&psq,  g_psq);

    // 1. prep
    prep_kernel<<<(NP*KNN*DIMS + 255)/256, 256>>>(rep, pts, cvw, (const float*)d_in[15]);
    // 2. lift MLP (fused d1+d2)
    lift_fused_kernel<<<(NP*KNN)/128, 256>>>(pl, d1w, d1b, d2w, d2b, lift);
    // 3. X0 = relu(plf @ Wc + cv_b)    M=16384 K=48 N=256
    sgemm_kernel<128,128,16,8,8,true,true><<<dim3(2,128), 256>>>(pl, wc, cvb, Xa, NP, KK, 48);
    // 4. X1 = relu(X0 @ x1 + b)
    sgemm_kernel<128,128,16,8,8,true,true><<<dim3(2,128), 256>>>(Xa, x1w, x1b, Xb, NP, KK, KK);
    // 5. X2 = X1 @ x2 + b
    sgemm_kernel<128,128,16,8,8,false,true><<<dim3(2,128), 256>>>(Xb, x2w, x2b, Xa, NP, KK, KK);
    // 6. per-point transform + depthwise
    xform_dw_kernel<<<NP/DPTS, 128>>>(Xa, lift, fts, dww, dwb, dw);
    // 7. pointwise GEMM + relu + BN partials
    sgemm_pw_stats<<<dim3(2,128), 256>>>(dw, pwT, out, psum, psq);
    // 8. BN stats
    stats_kernel<<<1, 256>>>(psum, psq, bng, bnb);
    // 9. BN apply
    bn_apply_kernel<<<(NP*(C_OUT/4) + 255)/256, 256>>>(out);
}

// round 3
// speedup vs baseline: 1.9999x; 1.9999x over previous
#include <cuda_runtime.h>
#include <math.h>

// ---------------- problem constants ----------------
#define NB    16
#define PP    1024
#define NP    (NB*PP)          // 16384
#define KNN   16
#define DIMS  3
#define C_IN  128
#define C_MID 64
#define C_CAT 192
#define C_OUT 256
#define DM    2
#define CD    384
#define KK    256
#define EPSBN 1e-5f

// ---------------- scratch ----------------
__device__ float g_pl   [NP*KNN*DIMS];
__device__ float g_lift [NP*KNN*C_MID];
__device__ float g_Xa   [NP*KK];
__device__ float g_Xb   [NP*KK];
__device__ float g_dw   [NP*CD];
__device__ float g_wc   [48*KK];
__device__ float g_pwT  [CD*C_OUT];
__device__ float g_psum [C_OUT*128];
__device__ float g_psq  [C_OUT*128];
__device__ float g_scale[C_OUT];
__device__ float g_shift[C_OUT];

typedef unsigned long long u64;

__device__ __forceinline__ u64 dup2(float x) {
    u64 r; asm("mov.b64 %0,{%1,%1};" : "=l"(r) : "f"(x)); return r;
}
__device__ __forceinline__ void fma2(u64& d, u64 a, u64 b) {
    asm("fma.rn.f32x2 %0,%1,%2,%0;" : "+l"(d) : "l"(a), "l"(b));
}
__device__ __forceinline__ float2 unp2(u64 v) {
    float2 r; asm("mov.b64 {%0,%1},%2;" : "=f"(r.x), "=f"(r.y) : "l"(v)); return r;
}

// ---------------- prep ----------------
__global__ void prep_kernel(const float* __restrict__ rep, const float* __restrict__ pts,
                            const float* __restrict__ cvw, const float* __restrict__ pww) {
    int idx = blockIdx.x * blockDim.x + threadIdx.x;
    if (idx < NP*KNN*DIMS) {
        int d  = idx % DIMS;
        int pk = idx / DIMS;
        int p  = pk / KNN;
        g_pl[idx] = pts[idx] - rep[p*DIMS + d];
    }
    if (idx < 48*KK) {
        int o = idx % KK, j = idx / KK;
        int k = j / 3, d = j % 3;
        g_wc[idx] = cvw[o*48 + d*KNN + k];
    }
    if (idx < CD*C_OUT) {
        int o = idx % C_OUT, j = idx / C_OUT;
        g_pwT[idx] = pww[o*CD + j];
    }
}

// ---------------- 128x128x16 f32x2 mainloop (256 threads) ----------------
__device__ __forceinline__ void mainloop128(
    const float* __restrict__ A, const float* __restrict__ B,
    int K, int N, int rowBase, int colBase,
    float (*As)[132], float (*Bs)[128],
    u64 acc[8][4], int tid, int tx, int ty)
{
    for (int k0 = 0; k0 < K; k0 += 16) {
        float4 a4[2], b4[2];
        #pragma unroll
        for (int t = 0; t < 2; t++) {
            int e = tid + t*256;
            int ar = e >> 2, ac = (e & 3) * 4;
            a4[t] = *(const float4*)&A[(size_t)(rowBase + ar)*K + k0 + ac];
            int br = e >> 5, bc = (e & 31) * 4;
            b4[t] = *(const float4*)&B[(size_t)(k0 + br)*N + colBase + bc];
        }
        __syncthreads();
        #pragma unroll
        for (int t = 0; t < 2; t++) {
            int e = tid + t*256;
            int ar = e >> 2, ac = (e & 3) * 4;
            As[ac+0][ar] = a4[t].x; As[ac+1][ar] = a4[t].y;
            As[ac+2][ar] = a4[t].z; As[ac+3][ar] = a4[t].w;
            int br = e >> 5, bc = (e & 31) * 4;
            *(float4*)&Bs[br][bc] = b4[t];
        }
        __syncthreads();
        #pragma unroll
        for (int kk = 0; kk < 16; kk++) {
            float4 x0 = *(const float4*)&As[kk][ty*8];
            float4 x1 = *(const float4*)&As[kk][ty*8 + 4];
            u64 ra[8];
            ra[0]=dup2(x0.x); ra[1]=dup2(x0.y); ra[2]=dup2(x0.z); ra[3]=dup2(x0.w);
            ra[4]=dup2(x1.x); ra[5]=dup2(x1.y); ra[6]=dup2(x1.z); ra[7]=dup2(x1.w);
            const u64* bp = (const u64*)&Bs[kk][tx*8];
            u64 rb0 = bp[0], rb1 = bp[1], rb2 = bp[2], rb3 = bp[3];
            #pragma unroll
            for (int i = 0; i < 8; i++) {
                fma2(acc[i][0], ra[i], rb0);
                fma2(acc[i][1], ra[i], rb1);
                fma2(acc[i][2], ra[i], rb2);
                fma2(acc[i][3], ra[i], rb3);
            }
        }
    }
    __syncthreads();
}

// ---------------- generic GEMM (BM=BN=128) ----------------
template<bool RELU, bool BIAS>
__global__ __launch_bounds__(256, 2)
void gemm128_kernel(const float* __restrict__ A, const float* __restrict__ B,
                    const float* __restrict__ bias, float* __restrict__ C,
                    int K, int N)
{
    __shared__ float As[16][132];
    __shared__ float Bs[16][128];
    const int tid = threadIdx.x, tx = tid & 15, ty = tid >> 4;
    const int rowBase = blockIdx.y * 128, colBase = blockIdx.x * 128;
    u64 acc[8][4];
    #pragma unroll
    for (int i = 0; i < 8; i++)
        #pragma unroll
        for (int j = 0; j < 4; j++) acc[i][j] = 0ull;

    mainloop128(A, B, K, N, rowBase, colBase, As, Bs, acc, tid, tx, ty);

    const int col = colBase + tx*8;
    #pragma unroll
    for (int i = 0; i < 8; i++) {
        int row = rowBase + ty*8 + i;
        float o[8];
        #pragma unroll
        for (int jp = 0; jp < 4; jp++) {
            float2 v = unp2(acc[i][jp]);
            o[2*jp] = v.x; o[2*jp+1] = v.y;
        }
        #pragma unroll
        for (int j = 0; j < 8; j++) {
            if (BIAS) o[j] += bias[col + j];
            if (RELU) o[j] = fmaxf(o[j], 0.f);
        }
        *(float4*)&C[(size_t)row*N + col    ] = make_float4(o[0],o[1],o[2],o[3]);
        *(float4*)&C[(size_t)row*N + col + 4] = make_float4(o[4],o[5],o[6],o[7]);
    }
}

// ---------------- pointwise GEMM + ReLU + BN partials ----------------
__global__ __launch_bounds__(256, 2)
void gemm_pw_stats(const float* __restrict__ A, const float* __restrict__ B,
                   float* __restrict__ C,
                   float* __restrict__ psum, float* __restrict__ psq)
{
    __shared__ float As[16][132];
    __shared__ float Bs[16][128];
    const int tid = threadIdx.x, tx = tid & 15, ty = tid >> 4;
    const int rowBase = blockIdx.y * 128, colBase = blockIdx.x * 128;
    u64 acc[8][4];
    #pragma unroll
    for (int i = 0; i < 8; i++)
        #pragma unroll
        for (int j = 0; j < 4; j++) acc[i][j] = 0ull;

    mainloop128(A, B, CD, C_OUT, rowBase, colBase, As, Bs, acc, tid, tx, ty);

    const int col = colBase + tx*8;
    float cs[8], cq[8];
    #pragma unroll
    for (int j = 0; j < 8; j++) { cs[j] = 0.f; cq[j] = 0.f; }
    #pragma unroll
    for (int i = 0; i < 8; i++) {
        int row = rowBase + ty*8 + i;
        float o[8];
        #pragma unroll
        for (int jp = 0; jp < 4; jp++) {
            float2 v = unp2(acc[i][jp]);
            o[2*jp] = v.x; o[2*jp+1] = v.y;
        }
        #pragma unroll
        for (int j = 0; j < 8; j++) {
            o[j] = fmaxf(o[j], 0.f);
            cs[j] += o[j];
            cq[j] += o[j]*o[j];
        }
        *(float4*)&C[(size_t)row*C_OUT + col    ] = make_float4(o[0],o[1],o[2],o[3]);
        *(float4*)&C[(size_t)row*C_OUT + col + 4] = make_float4(o[4],o[5],o[6],o[7]);
    }
    float* sb = &As[0][0];
    float* qb = &Bs[0][0];
    #pragma unroll
    for (int j = 0; j < 8; j++) {
        sb[ty*128 + tx*8 + j] = cs[j];
        qb[ty*128 + tx*8 + j] = cq[j];
    }
    __syncthreads();
    if (tid < 128) {
        float s = 0.f, q = 0.f;
        #pragma unroll
        for (int t = 0; t < 16; t++) { s += sb[t*128 + tid]; q += qb[t*128 + tid]; }
        psum[(colBase + tid)*128 + blockIdx.y] = s;
        psq [(colBase + tid)*128 + blockIdx.y] = q;
    }
}

// ---------------- fused lift MLP (BM=128, BN=64, 128 threads) ----------------
__global__ __launch_bounds__(128, 4)
void lift_fused_kernel(const float* __restrict__ pl,
                       const float* __restrict__ d1w, const float* __restrict__ d1b,
                       const float* __restrict__ d2w, const float* __restrict__ d2b,
                       float* __restrict__ out)
{
    __shared__ float As[16][132];
    __shared__ float Bs[16][64];
    const int tid = threadIdx.x, tx = tid & 7, ty = tid >> 3;
    const int rowBase = blockIdx.x * 128;
    u64 acc[8][4];
    #pragma unroll
    for (int i = 0; i < 8; i++)
        #pragma unroll
        for (int j = 0; j < 4; j++) acc[i][j] = 0ull;

    for (int k0 = 0; k0 < C_MID; k0 += 16) {
        __syncthreads();
        #pragma unroll
        for (int t = 0; t < 4; t++) {
            int e = tid + t*128;
            int ar = e >> 2, ac = (e & 3) * 4;
            int row = rowBase + ar;
            float p0 = pl[row*3+0], p1 = pl[row*3+1], p2 = pl[row*3+2];
            #pragma unroll
            for (int u = 0; u < 4; u++) {
                int kc = k0 + ac + u;
                float h = fmaf(p0, d1w[kc], fmaf(p1, d1w[64+kc], fmaf(p2, d1w[128+kc], d1b[kc])));
                As[ac+u][ar] = fmaxf(h, 0.f);
            }
        }
        #pragma unroll
        for (int t = 0; t < 2; t++) {
            int e = tid + t*128;
            int br = e >> 4, bc = (e & 15) * 4;
            *(float4*)&Bs[br][bc] = *(const float4*)&d2w[(k0 + br)*C_MID + bc];
        }
        __syncthreads();
        #pragma unroll
        for (int kk = 0; kk < 16; kk++) {
            float4 x0 = *(const float4*)&As[kk][ty*8];
            float4 x1 = *(const float4*)&As[kk][ty*8 + 4];
            u64 ra[8];
            ra[0]=dup2(x0.x); ra[1]=dup2(x0.y); ra[2]=dup2(x0.z); ra[3]=dup2(x0.w);
            ra[4]=dup2(x1.x); ra[5]=dup2(x1.y); ra[6]=dup2(x1.z); ra[7]=dup2(x1.w);
            const u64* bp = (const u64*)&Bs[kk][tx*8];
            u64 rb0 = bp[0], rb1 = bp[1], rb2 = bp[2], rb3 = bp[3];
            #pragma unroll
            for (int i = 0; i < 8; i++) {
                fma2(acc[i][0], ra[i], rb0);
                fma2(acc[i][1], ra[i], rb1);
                fma2(acc[i][2], ra[i], rb2);
                fma2(acc[i][3], ra[i], rb3);
            }
        }
    }
    const int col = tx*8;
    #pragma unroll
    for (int i = 0; i < 8; i++) {
        int row = rowBase + ty*8 + i;
        float o[8];
        #pragma unroll
        for (int jp = 0; jp < 4; jp++) {
            float2 v = unp2(acc[i][jp]);
            o[2*jp] = v.x; o[2*jp+1] = v.y;
        }
        #pragma unroll
        for (int j = 0; j < 8; j++) o[j] = fmaxf(o[j] + d2b[col + j], 0.f);
        *(float4*)&out[(size_t)row*C_MID + col    ] = make_float4(o[0],o[1],o[2],o[3]);
        *(float4*)&out[(size_t)row*C_MID + col + 4] = make_float4(o[4],o[5],o[6],o[7]);
    }
}

// ---------------- per-point X-transform + depthwise ----------------
#define DPTS 4
__global__ void xform_dw_kernel(const float* __restrict__ X2,
                                const float* __restrict__ lift,
                                const float* __restrict__ fts,
                                const float* __restrict__ dww,
                                const float* __restrict__ dwb,
                                float* __restrict__ dwout) {
    __shared__ float s_dwt[32*C_CAT];
    __shared__ float s_fc[KNN][C_CAT];
    __shared__ float s_X[KK];
    const int tid = threadIdx.x;          // 192 threads

    for (int e = tid; e < 32*C_CAT; e += 192) {
        int mi = e / C_CAT, c = e % C_CAT;
        s_dwt[mi*C_CAT + c] = dww[c*32 + mi];
    }

    for (int pp = 0; pp < DPTS; pp++) {
        int p = blockIdx.x * DPTS + pp;
        for (int e = tid; e < KK; e += 192) s_X[e] = X2[(size_t)p*KK + e];
        for (int e = tid; e < KNN*C_CAT; e += 192) {
            int j = e / C_CAT, c = e % C_CAT;
            s_fc[j][c] = (c < C_MID) ? lift[(size_t)p*(KNN*C_MID) + j*C_MID + c]
                                     : fts [(size_t)p*(KNN*C_IN) + j*C_IN + (c - C_MID)];
        }
        __syncthreads();
        {
            int c = tid;   // 0..191, exactly C_CAT threads
            float v[KNN];
            #pragma unroll
            for (int i = 0; i < KNN; i++) v[i] = 0.f;
            #pragma unroll
            for (int j = 0; j < KNN; j++) {
                float f = s_fc[j][c];
                #pragma unroll
                for (int i = 0; i < KNN; i++) v[i] += s_X[i*KNN + j] * f;
            }
            #pragma unroll
            for (int m = 0; m < DM; m++) {
                float s = 0.f;
                #pragma unroll
                for (int i = 0; i < KNN; i++) s += v[i] * s_dwt[(m*16 + i)*C_CAT + c];
                dwout[(size_t)p*CD + c*DM + m] = s + dwb[c*DM + m];
            }
        }
        __syncthreads();
    }
}

// ---------------- BN stats -> scale/shift ----------------
__global__ void stats_kernel(const float* __restrict__ psum, const float* __restrict__ psq,
                             const float* __restrict__ bng, const float* __restrict__ bnb) {
    int o = threadIdx.x;
    float s = 0.f, q = 0.f;
    for (int t = 0; t < 128; t++) { s += psum[o*128 + t]; q += psq[o*128 + t]; }
    float mean = s * (1.f / (float)NP);
    float var  = q * (1.f / (float)NP) - mean*mean;
    float sc   = bng[o] * rsqrtf(var + EPSBN);
    g_scale[o] = sc;
    g_shift[o] = bnb[o] - mean*sc;
}

// ---------------- BN apply ----------------
__global__ void bn_apply_kernel(float* __restrict__ out) {
    int idx = blockIdx.x * blockDim.x + threadIdx.x;
    if (idx >= NP*(C_OUT/4)) return;
    int c4 = (idx & 63) * 4;
    float4 v = reinterpret_cast<float4*>(out)[idx];
    v.x = v.x * g_scale[c4+0] + g_shift[c4+0];
    v.y = v.y * g_scale[c4+1] + g_shift[c4+1];
    v.z = v.z * g_scale[c4+2] + g_shift[c4+2];
    v.w = v.w * g_scale[c4+3] + g_shift[c4+3];
    reinterpret_cast<float4*>(out)[idx] = v;
}

// ---------------- launch ----------------
extern "C" void kernel_launch(void* const* d_in, const int* in_sizes, int n_in,
                              void* d_out, int out_size) {
    const float* rep  = (const float*)d_in[0];
    const float* pts  = (const float*)d_in[1];
    const float* fts  = (const float*)d_in[2];
    const float* d1w  = (const float*)d_in[3];
    const float* d1b  = (const float*)d_in[4];
    const float* d2w  = (const float*)d_in[5];
    const float* d2b  = (const float*)d_in[6];
    const float* cvw  = (const float*)d_in[7];
    const float* cvb  = (const float*)d_in[8];
    const float* x1w  = (const float*)d_in[9];
    const float* x1b  = (const float*)d_in[10];
    const float* x2w  = (const float*)d_in[11];
    const float* x2b  = (const float*)d_in[12];
    const float* dww  = (const float*)d_in[13];
    const float* dwb  = (const float*)d_in[14];
    const float* bng  = (const float*)d_in[16];
    const float* bnb  = (const float*)d_in[17];
    float* out = (float*)d_out;

    float *pl, *lift, *Xa, *Xb, *dw, *wc, *pwT, *psum, *psq;
    cudaGetSymbolAddress((void**)&pl,   g_pl);
    cudaGetSymbolAddress((void**)&lift, g_lift);
    cudaGetSymbolAddress((void**)&Xa,   g_Xa);
    cudaGetSymbolAddress((void**)&Xb,   g_Xb);
    cudaGetSymbolAddress((void**)&dw,   g_dw);
    cudaGetSymbolAddress((void**)&wc,   g_wc);
    cudaGetSymbolAddress((void**)&pwT,  g_pwT);
    cudaGetSymbolAddress((void**)&psum, g_psum);
    cudaGetSymbolAddress((void**)&psq,  g_psq);

    prep_kernel<<<(NP*KNN*DIMS + 255)/256, 256>>>(rep, pts, cvw, (const float*)d_in[15]);
    lift_fused_kernel<<<(NP*KNN)/128, 128>>>(pl, d1w, d1b, d2w, d2b, lift);
    gemm128_kernel<true,  true><<<dim3(2,128), 256>>>(pl, wc, cvb, Xa, 48, KK);
    gemm128_kernel<true,  true><<<dim3(2,128), 256>>>(Xa, x1w, x1b, Xb, KK, KK);
    gemm128_kernel<false, true><<<dim3(2,128), 256>>>(Xb, x2w, x2b, Xa, KK, KK);
    xform_dw_kernel<<<NP/DPTS, 192>>>(Xa, lift, fts, dww, dwb, dw);
    gemm_pw_stats<<<dim3(2,128), 256>>>(dw, pwT, out, psum, psq);
    stats_kernel<<<1, 256>>>(psum, psq, bng, bnb);
    bn_apply_kernel<<<(NP*(C_OUT/4) + 255)/256, 256>>>(out);
}